// round 8
// baseline (speedup 1.0000x reference)
#include <cuda_runtime.h>

#define NTOT   32768      // 64 graphs * 512 nodes
#define NB     64
#define NPG    512
#define LIG    128
#define GN_PER_G 1020
#define GG_PER_G 2
#define GFIXPG (GN_PER_G + GG_PER_G)          // 1022
#define GFIX   (NB * GFIXPG)                  // 65408
#define FULL   0xffffffffu
#define CAP    2816                           // staging slots per section (45KB total)

// d = __fsqrt_rn(d2);  d <= 8  <=>  d2 <= 64+1ulp ;  d <= 10 <=> d2 <= 100+1ulp
#define T8_BITS  0x42800001
#define T10_BITS 0x42C80001

// Scratch (device globals; zero-initialized at load; d_arrive self-resets)
__device__ unsigned d_mask_ctx[NTOT * 16];
__device__ unsigned d_mask_inter[NTOT * 16];
__device__ int d_cnt_ctx[NTOT];
__device__ int d_cnt_inter[NTOT];
__device__ int d_off_ctx[NTOT];     // within-graph exclusive row offsets
__device__ int d_off_inter[NTOT];
__device__ int d_graph_ctx[NB];
__device__ int d_graph_inter[NB];
__device__ int d_red_cnt[NB];
__device__ int d_arrive[NB];

__device__ __forceinline__ int warp_incl_scan(int x) {
    #pragma unroll
    for (int d = 1; d < 32; d <<= 1) {
        int y = __shfl_up_sync(FULL, x, d);
        if ((threadIdx.x & 31) >= d) x += y;
    }
    return x;
}

// One warp scans a 64-int array: exclusive prefix -> sh_excl[64], total -> *sh_tot.
__device__ __forceinline__ void warp_scan64_sh(const int* __restrict__ in,
                                               int* sh_excl, int* sh_tot) {
    int lane = threadIdx.x & 31;
    int v0 = in[2 * lane], v1 = in[2 * lane + 1];
    int s = v0 + v1;
    int x = warp_incl_scan(s);
    int excl = x - s;
    sh_excl[2 * lane]     = excl;
    sh_excl[2 * lane + 1] = excl + v0;
    if (lane == 31) *sh_tot = x;
}

// ---- count: 8 rows per warp, 64 rows per block (256 thr), fused scan ----
__global__ void __launch_bounds__(256) count_kernel(const float* __restrict__ X) {
    __shared__ float4 s_pos[NPG];
    __shared__ int sw[8];
    __shared__ int s_last, s_red;
    int tid  = threadIdx.x, lane = tid & 31, wid = tid >> 5;
    int blk  = blockIdx.x;                     // 512 blocks, 8 per graph
    int b    = blk >> 3;
    int base = b << 9;
    int r0   = (blk & 7) * 64 + wid * 8;       // first of this warp's 8 rows

    {
        const float* gp = X + 3 * base;
        #pragma unroll
        for (int t = tid; t < NPG; t += 256)
            s_pos[t] = make_float4(gp[3 * t], gp[3 * t + 1], gp[3 * t + 2], 0.f);
    }
    __syncthreads();

    const float t8  = __int_as_float(T8_BITS);
    const float t10 = __int_as_float(T10_BITS);

    float4 a[8];
    float  hi[8];
    unsigned mb[8];
    #pragma unroll
    for (int r = 0; r < 8; r++) {
        a[r]  = s_pos[r0 + r];
        hi[r] = (r0 + r > LIG) ? t8 : t10;
        mb[r] = 0u;
    }

    #pragma unroll
    for (int k = 0; k < 16; k++) {
        float4 p = s_pos[k * 32 + lane];
        #pragma unroll
        for (int r = 0; r < 8; r++) {
            float dx = __fadd_rn(a[r].x, -p.x);
            float dy = __fadd_rn(a[r].y, -p.y);
            float dz = __fadd_rn(a[r].z, -p.z);
            float d2 = __fadd_rn(__fadd_rn(__fmul_rn(dx, dx), __fmul_rn(dy, dy)),
                                 __fmul_rn(dz, dz));
            float thr = (k < 4) ? t10 : hi[r];
            unsigned m = __ballot_sync(FULL, d2 <= thr);
            if (lane == k) mb[r] = m;
        }
    }

    // classification (lane < 16 holds word `lane` of each row)
    unsigned LIGWl  = (lane == 0) ? 0xFFFFFFFEu : ((lane < 4)  ? FULL : 0u);
    unsigned PROTWl = (lane < 4)  ? 0u          : ((lane == 4) ? 0xFFFFFFFEu : FULL);

    #pragma unroll
    for (int r = 0; r < 8; r++) {
        int li = r0 + r, i = base + li;
        unsigned pm = (li > LIG) ? FULL : 0u;
        unsigned lm = (li >= 1 && li < LIG) ? FULL : 0u;
        unsigned myc  = mb[r] & PROTWl & pm;
        unsigned mymi = (mb[r] & LIGWl & pm) | (mb[r] & PROTWl & lm);
        if (pm && lane == (li >> 5)) myc &= ~(1u << (li & 31));   // remove self
        if (lane < 16) {
            d_mask_ctx[(i << 4) + lane]   = myc;
            d_mask_inter[(i << 4) + lane] = mymi;
        }
        int val = (lane < 16) ? (__popc(myc) | (__popc(mymi) << 16)) : 0;
        #pragma unroll
        for (int d = 16; d; d >>= 1) val += __shfl_down_sync(FULL, val, d);
        if (lane == 0) {
            d_cnt_ctx[i]   = val & 0xffff;
            d_cnt_inter[i] = val >> 16;
        }
    }

    // ---- last arriving block of this graph: per-graph scans (2 rows/thread) ----
    __syncthreads();
    if (tid == 0) {
        __threadfence();
        s_last = atomicAdd(&d_arrive[b], 1);
        s_red  = 0;
    }
    __syncthreads();
    if (s_last == 7) {
        __threadfence();
        int t = tid;

        // ctx scan
        int vc0 = d_cnt_ctx[base + 2 * t], vc1 = d_cnt_ctx[base + 2 * t + 1];
        int s2 = vc0 + vc1;
        int x = warp_incl_scan(s2);
        if (lane == 31) sw[wid] = x;
        __syncthreads();
        if (wid == 0) {
            int v = (lane < 8) ? sw[lane] : 0;
            v = warp_incl_scan(v);
            if (lane < 8) sw[lane] = v;
        }
        __syncthreads();
        int incl = x + (wid ? sw[wid - 1] : 0);
        int excl = incl - s2;
        d_off_ctx[base + 2 * t]     = excl;
        d_off_ctx[base + 2 * t + 1] = excl + vc0;
        if (t == 255) d_graph_ctx[b] = incl;
        __syncthreads();

        // inter scan
        int vi0 = d_cnt_inter[base + 2 * t], vi1 = d_cnt_inter[base + 2 * t + 1];
        s2 = vi0 + vi1;
        x = warp_incl_scan(s2);
        if (lane == 31) sw[wid] = x;
        __syncthreads();
        if (wid == 0) {
            int v = (lane < 8) ? sw[lane] : 0;
            v = warp_incl_scan(v);
            if (lane < 8) sw[lane] = v;
        }
        __syncthreads();
        incl = x + (wid ? sw[wid - 1] : 0);
        excl = incl - s2;
        d_off_inter[base + 2 * t]     = excl;
        d_off_inter[base + 2 * t + 1] = excl + vi0;
        if (t == 255) d_graph_inter[b] = incl;

        // reduced = ligand-row (1..127) inter edges
        int vr = ((2 * t >= 1 && 2 * t < LIG) ? vi0 : 0)
               + ((2 * t + 1 >= 1 && 2 * t + 1 < LIG) ? vi1 : 0);
        #pragma unroll
        for (int d = 16; d; d >>= 1) vr += __shfl_down_sync(FULL, vr, d);
        if (lane == 0 && vr) atomicAdd(&s_red, vr);
        __syncthreads();
        if (t == 0) {
            d_red_cnt[b] = s_red;
            d_arrive[b]  = 0;                   // reset for next graph replay
        }
    }
}

// ---- write: 2 rows/warp, active-word compression, smem-staged coalesced out ----
__global__ void __launch_bounds__(512) write_kernel(float* __restrict__ out) {
    __shared__ int sgc[NB], sgi[NB], sro[NB];
    __shared__ int stc_, sti_, str_;
    __shared__ float st[4 * CAP];               // 45KB staging
    int tid = threadIdx.x, lane = tid & 31, wid = tid >> 5;
    int blk  = blockIdx.x;                      // 1024 blocks
    int b    = blk >> 4;
    int s    = blk & 15;                        // slice 0..15 of graph
    int base = b << 9;
    int r0   = s * 32;

    if (wid == 0)      warp_scan64_sh(d_graph_ctx,   sgc, &stc_);
    else if (wid == 1) warp_scan64_sh(d_graph_inter, sgi, &sti_);
    else if (wid == 2) warp_scan64_sh(d_red_cnt,     sro, &str_);
    __syncthreads();

    int EcR = stc_;
    int Ec  = EcR + GFIX;
    int Ei  = sti_;
    int Er  = str_;

    int half = lane >> 4;
    int slot = lane & 15;
    int li   = r0 + wid * 2 + half;             // local row within graph
    int i    = base + li;

    bool prot = li > LIG;
    bool lig  = (li >= 1) && (li < LIG);
    int wIdx  = (slot < 12) ? (4 + slot) : (slot - 12);

    unsigned word = 0u;
    bool isCtx = false;
    if (prot) {
        word  = (slot < 12) ? d_mask_ctx[(i << 4) + wIdx]
                            : d_mask_inter[(i << 4) + wIdx];
        isCtx = slot < 12;
    } else if (lig && slot < 12) {
        word = d_mask_inter[(i << 4) + wIdx];
    }

    int cnt = __popc(word);
    int I   = warp_incl_scan(cnt);
    int I11 = __shfl_sync(FULL, I, 11);
    int I15 = __shfl_sync(FULL, I, 15);
    int I27 = __shfl_sync(FULL, I, 27);
    int sub0 = half ? I15 : 0;
    int sub1 = half ? I27 : I11;
    int excl = I - cnt - ((slot < 12) ? sub0 : sub1);

    // block-contiguous output ranges
    int cstart = d_off_ctx[base + r0];
    int cend   = (s == 15) ? d_graph_ctx[b]   : d_off_ctx[base + r0 + 32];
    int istart = d_off_inter[base + r0];
    int iend   = (s == 15) ? d_graph_inter[b] : d_off_inter[base + r0 + 32];
    int ctxTot = cend - cstart, intTot = iend - istart;

    float fi = (float)i;
    int cbase = base + wIdx * 32;

    if (ctxTot <= CAP && intTot <= CAP) {       // staged, coalesced path
        int loc, secR, secC;
        if (isCtx) { loc = d_off_ctx[i]   - cstart + excl; secR = 0;       secC = CAP; }
        else       { loc = d_off_inter[i] - istart + excl; secR = 2 * CAP; secC = 3 * CAP; }
        while (word) {
            int bit = __ffs(word) - 1;
            word &= word - 1;
            st[secR + loc] = fi;
            st[secC + loc] = (float)(cbase + bit);
            loc++;
        }
        __syncthreads();
        int cRowB = sgc[b] + cstart;
        int iRowB = 2 * Ec + sgi[b] + istart;
        for (int t = tid; t < ctxTot; t += 512) {
            out[cRowB + t]      = st[t];
            out[Ec + cRowB + t] = st[CAP + t];
        }
        for (int t = tid; t < intTot; t += 512) {
            out[iRowB + t]      = st[2 * CAP + t];
            out[iRowB + Ei + t] = st[3 * CAP + t];
        }
    } else {                                    // fallback: direct scattered writes
        int pos, colAdd;
        if (isCtx) { pos = sgc[b] + d_off_ctx[i] + excl;            colAdd = Ec; }
        else       { pos = 2 * Ec + sgi[b] + d_off_inter[i] + excl; colAdd = Ei; }
        while (word) {
            int bit = __ffs(word) - 1;
            word &= word - 1;
            out[pos]          = fi;
            out[pos + colAdd] = (float)(cbase + bit);
            pos++;
        }
    }

    // fixed global edges: slice s handles idx in [64s, 64s+64)
    if (tid < 64) {
        int idx = s * 64 + tid;
        if (idx < GFIXPG) {
            int r, c, p;
            if (idx < GN_PER_G) {
                p = EcR + b * GN_PER_G + idx;
                if (idx < 127)        { r = 0;               c = 1 + idx; }
                else if (idx < 254)   { r = idx - 126;       c = 0; }
                else if (idx < 637)   { r = 128;             c = idx - 254 + 129; }
                else                  { r = idx - 637 + 129; c = 128; }
            } else {
                int k = idx - GN_PER_G;
                p = EcR + NB * GN_PER_G + b * 2 + k;
                r = k ? 128 : 0;
                c = k ? 0   : 128;
            }
            out[p]      = (float)(base + r);
            out[Ec + p] = (float)(base + c);
        }
    }

    // reduced arrays: contiguous chunk per slice (coalesced)
    int rcnt = d_red_cnt[b];
    int roff = sro[b];
    int chunk = (rcnt + 15) >> 4;
    int k0 = s * chunk;
    int k1 = min(k0 + chunk, rcnt);
    int base1 = 2 * Ec + 2 * Ei + roff;
    int base2 = base1 + Er;
    float fb = (float)b, fo = (float)base;
    for (int k = k0 + tid; k < k1; k += 512) {
        out[base1 + k] = fb;
        out[base2 + k] = fo;
    }
}

extern "C" void kernel_launch(void* const* d_in, const int* in_sizes, int n_in,
                              void* d_out, int out_size) {
    const float* X = (const float*)d_in[0];
    for (int k = 0; k < n_in; k++) {
        if (in_sizes[k] == 3 * NTOT) { X = (const float*)d_in[k]; break; }
    }
    float* out = (float*)d_out;
    (void)out_size;

    count_kernel<<<NTOT / 64, 256>>>(X);
    write_kernel<<<NTOT / 32, 512>>>(out);
}